// round 14
// baseline (speedup 1.0000x reference)
#include <cuda_runtime.h>
#include <math.h>

// Problem constants (fixed by setup_inputs)
#define NN 100000
#define EE 1600000
#define HH 4
#define CC 16
#define DD 64
#define FF 128
#define ET_MAX (EE + NN)
#define NODES_PER_BLK 1024
#define MAX_SCAN_BLKS 128

// ---------------- scratch (device globals; no runtime allocation) ----------------
// INVARIANTS at kernel_launch entry (zero-init at load; restored every call):
//   g_deg  all-zero  (scan_lookback re-zeroes after consuming)
//   g_flag all-zero  (fat B's scatter part re-zeroes after scan completes)
// g_csr_src holds node indices; 16-entry zero pad allows clamp-free lookahead.
__device__ float g_xl[(size_t)NN * DD];
__device__ float g_xr[(size_t)NN * DD];
__device__ float g_h1[(size_t)NN * DD];
__device__ int   g_deg[NN];
__device__ int   g_off[NN + 1];
__device__ int   g_cur[NN];
__device__ unsigned g_flag[MAX_SCAN_BLKS];
__device__ int   g_csr_src[ET_MAX + 16];

// ---------------- helpers ----------------
__device__ __forceinline__ void ffma2(unsigned long long& acc,
                                      unsigned long long a, unsigned long long b) {
    asm("fma.rn.f32x2 %0, %1, %2, %0;" : "+l"(acc) : "l"(a), "l"(b));
}
__device__ __forceinline__ unsigned long long bcast2(float v) {
    unsigned long long r;
    asm("mov.b64 %0, {%1, %1};" : "=l"(r) : "r"(__float_as_uint(v)));
    return r;
}

// ================= GEMM body: 128 rows x (Wl||Wr 64+64 cols), 8x8 per thread =================
template<int K>
__device__ __forceinline__ void gemm_body(int blk,
                                          const float* __restrict__ X,
                                          const float* __restrict__ Wl,
                                          const float* __restrict__ Wr,
                                          float* __restrict__ xl,
                                          float* __restrict__ xr, int n,
                                          float (*As)[132], float (*Bs)[132]) {
    int tid = threadIdx.x;
    int rg = tid >> 4;
    int cg = tid & 15;
    int row0 = blk * 128;

    unsigned long long cl[8][2], cr[8][2];
#pragma unroll
    for (int i = 0; i < 8; i++) { cl[i][0] = cl[i][1] = cr[i][0] = cr[i][1] = 0ULL; }

    int lr  = tid >> 1;
    int lks = (tid & 1) * 8;
    int bk  = tid >> 4;
    int bc  = (tid & 15) * 8;

    for (int kc = 0; kc < K; kc += 16) {
        {
            int grow = row0 + lr;
            float4 v0 = make_float4(0.f, 0.f, 0.f, 0.f), v1 = v0;
            if (grow < n) {
                const float* g = X + (size_t)grow * K + kc + lks;
                v0 = *(const float4*)g;
                v1 = *(const float4*)(g + 4);
            }
            As[lks + 0][lr] = v0.x; As[lks + 1][lr] = v0.y;
            As[lks + 2][lr] = v0.z; As[lks + 3][lr] = v0.w;
            As[lks + 4][lr] = v1.x; As[lks + 5][lr] = v1.y;
            As[lks + 6][lr] = v1.z; As[lks + 7][lr] = v1.w;
        }
        {
            const float* wsrc = (bc < 64) ? (Wl + (size_t)(kc + bk) * DD + bc)
                                          : (Wr + (size_t)(kc + bk) * DD + (bc - 64));
            *(float4*)&Bs[bk][bc]     = *(const float4*)wsrc;
            *(float4*)&Bs[bk][bc + 4] = *(const float4*)(wsrc + 4);
        }
        __syncthreads();

#pragma unroll
        for (int k = 0; k < 16; k++) {
            float4 a01 = *(const float4*)&As[k][rg * 8];
            float4 a23 = *(const float4*)&As[k][rg * 8 + 4];
            ulonglong2 bl = *(const ulonglong2*)&Bs[k][cg * 4];
            ulonglong2 br = *(const ulonglong2*)&Bs[k][cg * 4 + 64];
            unsigned long long ab[8];
            ab[0] = bcast2(a01.x); ab[1] = bcast2(a01.y);
            ab[2] = bcast2(a01.z); ab[3] = bcast2(a01.w);
            ab[4] = bcast2(a23.x); ab[5] = bcast2(a23.y);
            ab[6] = bcast2(a23.z); ab[7] = bcast2(a23.w);
#pragma unroll
            for (int i = 0; i < 8; i++) {
                ffma2(cl[i][0], ab[i], bl.x); ffma2(cl[i][1], ab[i], bl.y);
                ffma2(cr[i][0], ab[i], br.x); ffma2(cr[i][1], ab[i], br.y);
            }
        }
        __syncthreads();
    }

#pragma unroll
    for (int i = 0; i < 8; i++) {
        int row = row0 + rg * 8 + i;
        if (row < n) {
            *(ulonglong2*)(xl + (size_t)row * DD + cg * 4) = make_ulonglong2(cl[i][0], cl[i][1]);
            *(ulonglong2*)(xr + (size_t)row * DD + cg * 4) = make_ulonglong2(cr[i][0], cr[i][1]);
        }
    }
}

// ---------------- hist body: 8 edges per thread ----------------
__device__ __forceinline__ void hist_body(int blk, const int* __restrict__ dst, int E) {
    int i = (blk * 256 + threadIdx.x) * 8;
    if (i + 7 < E) {
        int4 a = *(const int4*)(dst + i);
        int4 b = *(const int4*)(dst + i + 4);
        atomicAdd(&g_deg[a.x], 1); atomicAdd(&g_deg[a.y], 1);
        atomicAdd(&g_deg[a.z], 1); atomicAdd(&g_deg[a.w], 1);
        atomicAdd(&g_deg[b.x], 1); atomicAdd(&g_deg[b.y], 1);
        atomicAdd(&g_deg[b.z], 1); atomicAdd(&g_deg[b.w], 1);
    } else {
        for (int j = 0; j < 8; j++)
            if (i + j < E) atomicAdd(&g_deg[__ldg(dst + i + j)], 1);
    }
}

// ---------------- scatter body: 8 edges per thread (restores g_flag) ----------------
__device__ __forceinline__ void scatter_body(int blk, const int* __restrict__ src,
                                             const int* __restrict__ dst, int E) {
    if (blk == 0 && threadIdx.x < MAX_SCAN_BLKS)
        g_flag[threadIdx.x] = 0;
    int i = (blk * 256 + threadIdx.x) * 8;
    if (i + 7 < E) {
        int4 sa = *(const int4*)(src + i);
        int4 da = *(const int4*)(dst + i);
        int4 sb = *(const int4*)(src + i + 4);
        int4 db = *(const int4*)(dst + i + 4);
        int p0 = atomicAdd(&g_cur[da.x], 1);
        int p1 = atomicAdd(&g_cur[da.y], 1);
        int p2 = atomicAdd(&g_cur[da.z], 1);
        int p3 = atomicAdd(&g_cur[da.w], 1);
        int p4 = atomicAdd(&g_cur[db.x], 1);
        int p5 = atomicAdd(&g_cur[db.y], 1);
        int p6 = atomicAdd(&g_cur[db.z], 1);
        int p7 = atomicAdd(&g_cur[db.w], 1);
        g_csr_src[p0] = sa.x; g_csr_src[p1] = sa.y;
        g_csr_src[p2] = sa.z; g_csr_src[p3] = sa.w;
        g_csr_src[p4] = sb.x; g_csr_src[p5] = sb.y;
        g_csr_src[p6] = sb.z; g_csr_src[p7] = sb.w;
    } else {
        for (int j = 0; j < 8; j++)
            if (i + j < E) {
                int s = __ldg(src + i + j), d = __ldg(dst + i + j);
                g_csr_src[atomicAdd(&g_cur[d], 1)] = s;
            }
    }
}

// ================= fat kernel A: gemm1 first half (even blocks) + hist (odd) =============
__global__ __launch_bounds__(256, 2)
void fat_gemm_hist(const float* __restrict__ X,
                   const float* __restrict__ Wl,
                   const float* __restrict__ Wr,
                   float* __restrict__ xl, float* __restrict__ xr, int n,
                   const int* __restrict__ dst, int E,
                   int gemmBlk0, int gemmCnt, int gHist) {
    __shared__ float As[16][132];
    __shared__ float Bs[16][132];
    int bid = blockIdx.x;
    int g = bid >> 1;
    if ((bid & 1) == 0) {
        if (g < gemmCnt) gemm_body<FF>(gemmBlk0 + g, X, Wl, Wr, xl, xr, n, As, Bs);
    } else {
        if (g < gHist) hist_body(g, dst, E);
    }
}

// ================= fat kernel B: gemm1 second half (even blocks) + scatter (odd) =========
__global__ __launch_bounds__(256, 2)
void fat_gemm_scatter(const float* __restrict__ X,
                      const float* __restrict__ Wl,
                      const float* __restrict__ Wr,
                      float* __restrict__ xl, float* __restrict__ xr, int n,
                      const int* __restrict__ src, const int* __restrict__ dst, int E,
                      int gemmBlk0, int gemmCnt, int gScat) {
    __shared__ float As[16][132];
    __shared__ float Bs[16][132];
    int bid = blockIdx.x;
    int g = bid >> 1;
    if ((bid & 1) == 0) {
        if (g < gemmCnt) gemm_body<FF>(gemmBlk0 + g, X, Wl, Wr, xl, xr, n, As, Bs);
    } else {
        if (g < gScat) scatter_body(g, src, dst, E);
    }
}

// ================= standalone GEMM (layer 2) =================
template<int K>
__global__ __launch_bounds__(256, 2)
void gemm_tiled(const float* __restrict__ X,
                const float* __restrict__ Wl,
                const float* __restrict__ Wr,
                float* __restrict__ xl, float* __restrict__ xr, int n) {
    __shared__ float As[16][132];
    __shared__ float Bs[16][132];
    gemm_body<K>(blockIdx.x, X, Wl, Wr, xl, xr, n, As, Bs);
}

// ================= decoupled-lookback scan (one kernel) =================
__global__ void scan_lookback(int n, int nblk) {
    __shared__ int sh[256];
    __shared__ int s_prefix;
    int t = threadIdx.x, b = blockIdx.x;
    int i0 = b * NODES_PER_BLK + t * 4;

    int d0 = 0, d1 = 0, d2 = 0, d3 = 0;
    if (i0 + 3 < n) {
        int4 d = *(const int4*)(g_deg + i0);
        d0 = d.x + 1; d1 = d.y + 1; d2 = d.z + 1; d3 = d.w + 1;
        *(int4*)(g_deg + i0) = make_int4(0, 0, 0, 0);
    } else {
        if (i0 + 0 < n) { d0 = g_deg[i0 + 0] + 1; g_deg[i0 + 0] = 0; }
        if (i0 + 1 < n) { d1 = g_deg[i0 + 1] + 1; g_deg[i0 + 1] = 0; }
        if (i0 + 2 < n) { d2 = g_deg[i0 + 2] + 1; g_deg[i0 + 2] = 0; }
        if (i0 + 3 < n) { d3 = g_deg[i0 + 3] + 1; g_deg[i0 + 3] = 0; }
    }
    int tsum = d0 + d1 + d2 + d3;
    sh[t] = tsum; __syncthreads();
    for (int d = 1; d < 256; d <<= 1) {
        int v = (t >= d) ? sh[t - d] : 0;
        __syncthreads();
        sh[t] += v;
        __syncthreads();
    }
    int T = sh[255];

    volatile unsigned* flag = g_flag;
    if (t == 0) {
        if (b == 0) {
            s_prefix = 0;
            flag[0] = (2u << 30) | (unsigned)T;
        } else {
            flag[b] = (1u << 30) | (unsigned)T;
            unsigned run = 0;
            int j = b - 1;
            while (true) {
                unsigned v = flag[j];
                unsigned st = v >> 30;
                if (st == 0) continue;
                run += v & 0x3FFFFFFFu;
                if (st == 2u) break;
                j--;
            }
            s_prefix = (int)run;
            flag[b] = (2u << 30) | (run + (unsigned)T);
        }
    }
    __syncthreads();
    int base = s_prefix + sh[t] - tsum;

    int dd[4] = {d0, d1, d2, d3};
    int o = base;
    for (int j = 0; j < 4; j++) {
        int i = i0 + j;
        if (i < n) {
            g_off[i] = o;
            g_csr_src[o] = i;          // self loop first
            g_cur[i] = o + 1;
        }
        o += dd[j];
    }
    if (b == nblk - 1 && t == 255) g_off[n] = s_prefix + T;
}

// ================= fused GATv2 attention + aggregate + bias + ReLU =================
// NEW layout: warp per dst node; 8 lanes per edge, 4 edges per warp-step.
// Lane li (=lane&7) of quarter q (=lane>>3) owns dims [li*4..+3] (chunk A,
// head li>>2) and [32+li*4..+3] (chunk B, head 2+(li>>2)). Loads stay fully
// coalesced (each quarter covers one contiguous 128B half-row). Head sums via
// xor1+xor2 (1 SHFL/edge); per-head softmax sums tracked per lane (2 heads).
// Epilogue butterfly (xor 8,16) combines the 4 quarters.
__global__ void __launch_bounds__(256, 4)
gat_node(const float* __restrict__ xl,
         const float* __restrict__ xr,
         const float* __restrict__ att,
         const float* __restrict__ bias,
         float* __restrict__ out, int n) {
    int w    = (blockIdx.x * blockDim.x + threadIdx.x) >> 5;
    int lane = threadIdx.x & 31;
    if (w >= n) return;
    int q  = lane >> 3;       // edge slot within step (0..3)
    int li = lane & 7;        // lane within quarter

    const float* xrw = xr + (size_t)w * DD;
    float4 xA = *(const float4*)(xrw + li * 4);
    float4 xB = *(const float4*)(xrw + 32 + li * 4);
    float4 aA = *(const float4*)(att + li * 4);
    float4 aB = *(const float4*)(att + 32 + li * 4);

    int beg = g_off[w], end = g_off[w + 1];
    int rem = end - beg;
    const int* ip = g_csr_src + beg;

    float sA = 0.f, sB = 0.f;
    float4 cA = make_float4(0.f, 0.f, 0.f, 0.f), cB = cA;

    // prologue: rows for step 0, index for step 1 (pad covers overread)
    int c0 = __ldg(ip + q);
    const float* r0 = xl + (size_t)c0 * DD;
    float4 vA = *(const float4*)(r0 + li * 4);
    float4 vB = *(const float4*)(r0 + 32 + li * 4);
    int n0 = __ldg(ip + 4 + q);

    for (int i = 0; i < rem; i += 4) {
        // prefetch rows for step i+4, index for step i+8
        const float* r1 = xl + (size_t)n0 * DD;
        float4 wA = *(const float4*)(r1 + li * 4);
        float4 wB = *(const float4*)(r1 + 32 + li * 4);
        int m0 = __ldg(ip + i + 8 + q);

        float u, lA = 0.f, bA = 0.f, lB = 0.f, bB = 0.f;
        u = vA.x + xA.x; lA = fmaf(aA.x, u, lA); bA = fmaf(aA.x, fabsf(u), bA);
        u = vA.y + xA.y; lA = fmaf(aA.y, u, lA); bA = fmaf(aA.y, fabsf(u), bA);
        u = vA.z + xA.z; lA = fmaf(aA.z, u, lA); bA = fmaf(aA.z, fabsf(u), bA);
        u = vA.w + xA.w; lA = fmaf(aA.w, u, lA); bA = fmaf(aA.w, fabsf(u), bA);
        u = vB.x + xB.x; lB = fmaf(aB.x, u, lB); bB = fmaf(aB.x, fabsf(u), bB);
        u = vB.y + xB.y; lB = fmaf(aB.y, u, lB); bB = fmaf(aB.y, fabsf(u), bB);
        u = vB.z + xB.z; lB = fmaf(aB.z, u, lB); bB = fmaf(aB.z, fabsf(u), bB);
        u = vB.w + xB.w; lB = fmaf(aB.w, u, lB); bB = fmaf(aB.w, fabsf(u), bB);
        float tA = fmaf(0.6f, lA, 0.4f * bA);   // partial for head li>>2
        float tB = fmaf(0.6f, lB, 0.4f * bB);   // partial for head 2+(li>>2)

        // sum over the 4 lanes of each head group (stays within quarter)
        tA += __shfl_xor_sync(0xffffffffu, tA, 1);
        tB += __shfl_xor_sync(0xffffffffu, tB, 1);
        tA += __shfl_xor_sync(0xffffffffu, tA, 2);
        tB += __shfl_xor_sync(0xffffffffu, tB, 2);

        bool valid = (i + q < rem);
        float pA = valid ? __expf(tA) : 0.f;
        float pB = valid ? __expf(tB) : 0.f;
        sA += pA; sB += pB;
        cA.x = fmaf(pA, vA.x, cA.x); cA.y = fmaf(pA, vA.y, cA.y);
        cA.z = fmaf(pA, vA.z, cA.z); cA.w = fmaf(pA, vA.w, cA.w);
        cB.x = fmaf(pB, vB.x, cB.x); cB.y = fmaf(pB, vB.y, cB.y);
        cB.z = fmaf(pB, vB.z, cB.z); cB.w = fmaf(pB, vB.w, cB.w);

        vA = wA; vB = wB; n0 = m0;
    }

    // combine the 4 quarters (disjoint edge sets, same dims per li)
#pragma unroll
    for (int m = 8; m < 32; m <<= 1) {
        sA   += __shfl_xor_sync(0xffffffffu, sA,   m);
        sB   += __shfl_xor_sync(0xffffffffu, sB,   m);
        cA.x += __shfl_xor_sync(0xffffffffu, cA.x, m);
        cA.y += __shfl_xor_sync(0xffffffffu, cA.y, m);
        cA.z += __shfl_xor_sync(0xffffffffu, cA.z, m);
        cA.w += __shfl_xor_sync(0xffffffffu, cA.w, m);
        cB.x += __shfl_xor_sync(0xffffffffu, cB.x, m);
        cB.y += __shfl_xor_sync(0xffffffffu, cB.y, m);
        cB.z += __shfl_xor_sync(0xffffffffu, cB.z, m);
        cB.w += __shfl_xor_sync(0xffffffffu, cB.w, m);
    }

    if (q == 0) {
        float4 bvA = *(const float4*)(bias + li * 4);
        float4 bvB = *(const float4*)(bias + 32 + li * 4);
        float iA = __fdividef(1.f, sA);
        float iB = __fdividef(1.f, sB);
        float4 oA, oB;
        oA.x = fmaxf(fmaf(cA.x, iA, bvA.x), 0.f);
        oA.y = fmaxf(fmaf(cA.y, iA, bvA.y), 0.f);
        oA.z = fmaxf(fmaf(cA.z, iA, bvA.z), 0.f);
        oA.w = fmaxf(fmaf(cA.w, iA, bvA.w), 0.f);
        oB.x = fmaxf(fmaf(cB.x, iB, bvB.x), 0.f);
        oB.y = fmaxf(fmaf(cB.y, iB, bvB.y), 0.f);
        oB.z = fmaxf(fmaf(cB.z, iB, bvB.z), 0.f);
        oB.w = fmaxf(fmaf(cB.w, iB, bvB.w), 0.f);
        float* ow = out + (size_t)w * DD;
        *(float4*)(ow + li * 4) = oA;
        *(float4*)(ow + 32 + li * 4) = oB;
    }
}

// ---------------- launch ----------------
extern "C" void kernel_launch(void* const* d_in, const int* in_sizes, int n_in,
                              void* d_out, int out_size) {
    const float* x    = (const float*)d_in[0];
    const int*   edge = (const int*)  d_in[1];
    const float* W1l  = (const float*)d_in[2];
    const float* W1r  = (const float*)d_in[3];
    const float* att1 = (const float*)d_in[4];
    const float* b1   = (const float*)d_in[5];
    const float* W2l  = (const float*)d_in[6];
    const float* W2r  = (const float*)d_in[7];
    const float* att2 = (const float*)d_in[8];
    const float* b2   = (const float*)d_in[9];

    int E = in_sizes[1] / 2;
    int N = in_sizes[0] / FF;
    const int* srcp = edge;
    const int* dstp = edge + E;
    float* out = (float*)d_out;

    float *xl, *xr, *h1;
    cudaGetSymbolAddress((void**)&xl, g_xl);
    cudaGetSymbolAddress((void**)&xr, g_xr);
    cudaGetSymbolAddress((void**)&h1, g_h1);

    const int TB = 256;
    int gGemm = (N + 127) / 128;
    int gHalf1 = gGemm / 2;
    int gHalf2 = gGemm - gHalf1;
    int gEdge8 = (E + TB * 8 - 1) / (TB * 8);
    int nblk  = (N + NODES_PER_BLK - 1) / NODES_PER_BLK;
    int gNode = (N * 32 + TB - 1) / TB;
    int gFat1 = 2 * (gHalf1 > gEdge8 ? gHalf1 : gEdge8);
    int gFat2 = 2 * (gHalf2 > gEdge8 ? gHalf2 : gEdge8);

    // 1: gemm1 rows [0, N/2) + degree histogram (interleaved by block parity)
    fat_gemm_hist<<<gFat1, TB>>>(x, W1l, W1r, xl, xr, N, dstp, E, 0, gHalf1, gEdge8);
    // 2: CSR offsets via decoupled lookback (restores g_deg)
    scan_lookback<<<nblk, TB>>>(N, nblk);
    // 3: gemm1 rows [N/2, N) + CSR scatter (restores g_flag)
    fat_gemm_scatter<<<gFat2, TB>>>(x, W1l, W1r, xl, xr, N, srcp, dstp, E,
                                    gHalf1, gHalf2, gEdge8);
    // 4: layer-1 attention (profiled slot)
    gat_node<<<gNode, TB>>>(xl, xr, att1, b1, h1, N);
    // 5: layer-2 GEMM
    gemm_tiled<DD><<<gGemm, TB>>>(h1, W2l, W2r, xl, xr, N);
    // 6: layer-2 attention
    gat_node<<<gNode, TB>>>(xl, xr, att2, b2, out, N);
}

// round 15
// speedup vs baseline: 1.1371x; 1.1371x over previous
#include <cuda_runtime.h>
#include <math.h>

// Problem constants (fixed by setup_inputs)
#define NN 100000
#define EE 1600000
#define HH 4
#define CC 16
#define DD 64
#define FF 128
#define ET_MAX (EE + NN)
#define NODES_PER_BLK 1024
#define MAX_SCAN_BLKS 128

// ---------------- scratch (device globals; no runtime allocation) ----------------
// INVARIANTS at kernel_launch entry (zero-init at load; restored every call):
//   g_deg  all-zero  (scan_lookback re-zeroes after consuming)
//   g_flag all-zero  (fat B's scatter part re-zeroes after scan completes)
// g_csr_src holds node indices; 16-entry zero pad allows clamp-free lookahead.
__device__ float g_xl[(size_t)NN * DD];
__device__ float g_xr[(size_t)NN * DD];
__device__ float g_h1[(size_t)NN * DD];
__device__ int   g_deg[NN];
__device__ int   g_off[NN + 1];
__device__ int   g_cur[NN];
__device__ unsigned g_flag[MAX_SCAN_BLKS];
__device__ int   g_csr_src[ET_MAX + 16];

// ---------------- helpers ----------------
__device__ __forceinline__ void ffma2(unsigned long long& acc,
                                      unsigned long long a, unsigned long long b) {
    asm("fma.rn.f32x2 %0, %1, %2, %0;" : "+l"(acc) : "l"(a), "l"(b));
}
__device__ __forceinline__ unsigned long long bcast2(float v) {
    unsigned long long r;
    asm("mov.b64 %0, {%1, %1};" : "=l"(r) : "r"(__float_as_uint(v)));
    return r;
}

// ================= GEMM body: 128 rows x (Wl||Wr 64+64 cols), 8x8 per thread =================
template<int K>
__device__ __forceinline__ void gemm_body(int blk,
                                          const float* __restrict__ X,
                                          const float* __restrict__ Wl,
                                          const float* __restrict__ Wr,
                                          float* __restrict__ xl,
                                          float* __restrict__ xr, int n,
                                          float (*As)[132], float (*Bs)[132]) {
    int tid = threadIdx.x;
    int rg = tid >> 4;
    int cg = tid & 15;
    int row0 = blk * 128;

    unsigned long long cl[8][2], cr[8][2];
#pragma unroll
    for (int i = 0; i < 8; i++) { cl[i][0] = cl[i][1] = cr[i][0] = cr[i][1] = 0ULL; }

    int lr  = tid >> 1;
    int lks = (tid & 1) * 8;
    int bk  = tid >> 4;
    int bc  = (tid & 15) * 8;

    for (int kc = 0; kc < K; kc += 16) {
        {
            int grow = row0 + lr;
            float4 v0 = make_float4(0.f, 0.f, 0.f, 0.f), v1 = v0;
            if (grow < n) {
                const float* g = X + (size_t)grow * K + kc + lks;
                v0 = *(const float4*)g;
                v1 = *(const float4*)(g + 4);
            }
            As[lks + 0][lr] = v0.x; As[lks + 1][lr] = v0.y;
            As[lks + 2][lr] = v0.z; As[lks + 3][lr] = v0.w;
            As[lks + 4][lr] = v1.x; As[lks + 5][lr] = v1.y;
            As[lks + 6][lr] = v1.z; As[lks + 7][lr] = v1.w;
        }
        {
            const float* wsrc = (bc < 64) ? (Wl + (size_t)(kc + bk) * DD + bc)
                                          : (Wr + (size_t)(kc + bk) * DD + (bc - 64));
            *(float4*)&Bs[bk][bc]     = *(const float4*)wsrc;
            *(float4*)&Bs[bk][bc + 4] = *(const float4*)(wsrc + 4);
        }
        __syncthreads();

#pragma unroll
        for (int k = 0; k < 16; k++) {
            float4 a01 = *(const float4*)&As[k][rg * 8];
            float4 a23 = *(const float4*)&As[k][rg * 8 + 4];
            ulonglong2 bl = *(const ulonglong2*)&Bs[k][cg * 4];
            ulonglong2 br = *(const ulonglong2*)&Bs[k][cg * 4 + 64];
            unsigned long long ab[8];
            ab[0] = bcast2(a01.x); ab[1] = bcast2(a01.y);
            ab[2] = bcast2(a01.z); ab[3] = bcast2(a01.w);
            ab[4] = bcast2(a23.x); ab[5] = bcast2(a23.y);
            ab[6] = bcast2(a23.z); ab[7] = bcast2(a23.w);
#pragma unroll
            for (int i = 0; i < 8; i++) {
                ffma2(cl[i][0], ab[i], bl.x); ffma2(cl[i][1], ab[i], bl.y);
                ffma2(cr[i][0], ab[i], br.x); ffma2(cr[i][1], ab[i], br.y);
            }
        }
        __syncthreads();
    }

#pragma unroll
    for (int i = 0; i < 8; i++) {
        int row = row0 + rg * 8 + i;
        if (row < n) {
            *(ulonglong2*)(xl + (size_t)row * DD + cg * 4) = make_ulonglong2(cl[i][0], cl[i][1]);
            *(ulonglong2*)(xr + (size_t)row * DD + cg * 4) = make_ulonglong2(cr[i][0], cr[i][1]);
        }
    }
}

// ---------------- hist body: 8 edges per thread ----------------
__device__ __forceinline__ void hist_body(int blk, const int* __restrict__ dst, int E) {
    int i = (blk * 256 + threadIdx.x) * 8;
    if (i + 7 < E) {
        int4 a = *(const int4*)(dst + i);
        int4 b = *(const int4*)(dst + i + 4);
        atomicAdd(&g_deg[a.x], 1); atomicAdd(&g_deg[a.y], 1);
        atomicAdd(&g_deg[a.z], 1); atomicAdd(&g_deg[a.w], 1);
        atomicAdd(&g_deg[b.x], 1); atomicAdd(&g_deg[b.y], 1);
        atomicAdd(&g_deg[b.z], 1); atomicAdd(&g_deg[b.w], 1);
    } else {
        for (int j = 0; j < 8; j++)
            if (i + j < E) atomicAdd(&g_deg[__ldg(dst + i + j)], 1);
    }
}

// ---------------- scatter body: 8 edges per thread (restores g_flag) ----------------
__device__ __forceinline__ void scatter_body(int blk, const int* __restrict__ src,
                                             const int* __restrict__ dst, int E) {
    if (blk == 0 && threadIdx.x < MAX_SCAN_BLKS)
        g_flag[threadIdx.x] = 0;
    int i = (blk * 256 + threadIdx.x) * 8;
    if (i + 7 < E) {
        int4 sa = *(const int4*)(src + i);
        int4 da = *(const int4*)(dst + i);
        int4 sb = *(const int4*)(src + i + 4);
        int4 db = *(const int4*)(dst + i + 4);
        int p0 = atomicAdd(&g_cur[da.x], 1);
        int p1 = atomicAdd(&g_cur[da.y], 1);
        int p2 = atomicAdd(&g_cur[da.z], 1);
        int p3 = atomicAdd(&g_cur[da.w], 1);
        int p4 = atomicAdd(&g_cur[db.x], 1);
        int p5 = atomicAdd(&g_cur[db.y], 1);
        int p6 = atomicAdd(&g_cur[db.z], 1);
        int p7 = atomicAdd(&g_cur[db.w], 1);
        g_csr_src[p0] = sa.x; g_csr_src[p1] = sa.y;
        g_csr_src[p2] = sa.z; g_csr_src[p3] = sa.w;
        g_csr_src[p4] = sb.x; g_csr_src[p5] = sb.y;
        g_csr_src[p6] = sb.z; g_csr_src[p7] = sb.w;
    } else {
        for (int j = 0; j < 8; j++)
            if (i + j < E) {
                int s = __ldg(src + i + j), d = __ldg(dst + i + j);
                g_csr_src[atomicAdd(&g_cur[d], 1)] = s;
            }
    }
}

// ================= fat kernel A: gemm1 first half (even blocks) + hist (odd) =============
__global__ __launch_bounds__(256, 2)
void fat_gemm_hist(const float* __restrict__ X,
                   const float* __restrict__ Wl,
                   const float* __restrict__ Wr,
                   float* __restrict__ xl, float* __restrict__ xr, int n,
                   const int* __restrict__ dst, int E,
                   int gemmBlk0, int gemmCnt, int gHist) {
    __shared__ float As[16][132];
    __shared__ float Bs[16][132];
    int bid = blockIdx.x;
    int g = bid >> 1;
    if ((bid & 1) == 0) {
        if (g < gemmCnt) gemm_body<FF>(gemmBlk0 + g, X, Wl, Wr, xl, xr, n, As, Bs);
    } else {
        if (g < gHist) hist_body(g, dst, E);
    }
}

// ================= fat kernel B: gemm1 second half (even blocks) + scatter (odd) =========
__global__ __launch_bounds__(256, 2)
void fat_gemm_scatter(const float* __restrict__ X,
                      const float* __restrict__ Wl,
                      const float* __restrict__ Wr,
                      float* __restrict__ xl, float* __restrict__ xr, int n,
                      const int* __restrict__ src, const int* __restrict__ dst, int E,
                      int gemmBlk0, int gemmCnt, int gScat) {
    __shared__ float As[16][132];
    __shared__ float Bs[16][132];
    int bid = blockIdx.x;
    int g = bid >> 1;
    if ((bid & 1) == 0) {
        if (g < gemmCnt) gemm_body<FF>(gemmBlk0 + g, X, Wl, Wr, xl, xr, n, As, Bs);
    } else {
        if (g < gScat) scatter_body(g, src, dst, E);
    }
}

// ================= standalone GEMM (layer 2) =================
template<int K>
__global__ __launch_bounds__(256, 2)
void gemm_tiled(const float* __restrict__ X,
                const float* __restrict__ Wl,
                const float* __restrict__ Wr,
                float* __restrict__ xl, float* __restrict__ xr, int n) {
    __shared__ float As[16][132];
    __shared__ float Bs[16][132];
    gemm_body<K>(blockIdx.x, X, Wl, Wr, xl, xr, n, As, Bs);
}

// ================= decoupled-lookback scan (one kernel) =================
__global__ void scan_lookback(int n, int nblk) {
    __shared__ int sh[256];
    __shared__ int s_prefix;
    int t = threadIdx.x, b = blockIdx.x;
    int i0 = b * NODES_PER_BLK + t * 4;

    int d0 = 0, d1 = 0, d2 = 0, d3 = 0;
    if (i0 + 3 < n) {
        int4 d = *(const int4*)(g_deg + i0);
        d0 = d.x + 1; d1 = d.y + 1; d2 = d.z + 1; d3 = d.w + 1;
        *(int4*)(g_deg + i0) = make_int4(0, 0, 0, 0);
    } else {
        if (i0 + 0 < n) { d0 = g_deg[i0 + 0] + 1; g_deg[i0 + 0] = 0; }
        if (i0 + 1 < n) { d1 = g_deg[i0 + 1] + 1; g_deg[i0 + 1] = 0; }
        if (i0 + 2 < n) { d2 = g_deg[i0 + 2] + 1; g_deg[i0 + 2] = 0; }
        if (i0 + 3 < n) { d3 = g_deg[i0 + 3] + 1; g_deg[i0 + 3] = 0; }
    }
    int tsum = d0 + d1 + d2 + d3;
    sh[t] = tsum; __syncthreads();
    for (int d = 1; d < 256; d <<= 1) {
        int v = (t >= d) ? sh[t - d] : 0;
        __syncthreads();
        sh[t] += v;
        __syncthreads();
    }
    int T = sh[255];

    volatile unsigned* flag = g_flag;
    if (t == 0) {
        if (b == 0) {
            s_prefix = 0;
            flag[0] = (2u << 30) | (unsigned)T;
        } else {
            flag[b] = (1u << 30) | (unsigned)T;
            unsigned run = 0;
            int j = b - 1;
            while (true) {
                unsigned v = flag[j];
                unsigned st = v >> 30;
                if (st == 0) continue;
                run += v & 0x3FFFFFFFu;
                if (st == 2u) break;
                j--;
            }
            s_prefix = (int)run;
            flag[b] = (2u << 30) | (run + (unsigned)T);
        }
    }
    __syncthreads();
    int base = s_prefix + sh[t] - tsum;

    int dd[4] = {d0, d1, d2, d3};
    int o = base;
    for (int j = 0; j < 4; j++) {
        int i = i0 + j;
        if (i < n) {
            g_off[i] = o;
            g_csr_src[o] = i;          // self loop first
            g_cur[i] = o + 1;
        }
        o += dd[j];
    }
    if (b == nblk - 1 && t == 255) g_off[n] = s_prefix + T;
}

// ================= fused GATv2 attention + aggregate + bias + ReLU =================
// R12/R13 structure (best measured): warp per dst node; 16 lanes/edge, 2 edges
// per step, 2-deep pipeline, launch_bounds(256,5), 3-op scoring, clamp-free pad.
// NEW: main loop covers only FULL quads (no validity predicates); single
// predicated tail trip handles the remainder.
__global__ void __launch_bounds__(256, 5)
gat_node(const float* __restrict__ xl,
         const float* __restrict__ xr,
         const float* __restrict__ att,
         const float* __restrict__ bias,
         float* __restrict__ out, int n) {
    int w    = (blockIdx.x * blockDim.x + threadIdx.x) >> 5;
    int lane = threadIdx.x & 31;
    if (w >= n) return;
    int half = lane >> 4;
    int sub  = lane & 15;

    float4 xrv  = *(const float4*)(xr  + (size_t)w * DD + sub * 4);
    float4 attv = *(const float4*)(att + sub * 4);

    int beg = g_off[w], end = g_off[w + 1];
    int rem = end - beg;
    const int* ip = g_csr_src + beg;

    float s = 0.f, a0 = 0.f, a1 = 0.f, a2 = 0.f, a3 = 0.f;

    // pipeline prologue: rows for trip 0, indices for trip 1 (pad covers overread)
    int c0 = __ldg(ip + half);
    int c1 = __ldg(ip + 2 + half);
    float4 v0 = *(const float4*)(xl + (size_t)c0 * DD + sub * 4);
    float4 v1 = *(const float4*)(xl + (size_t)c1 * DD + sub * 4);
    int n0 = __ldg(ip + 4 + half);
    int n1 = __ldg(ip + 6 + half);

    int i = 0;
    // main loop: all 4 edges of the trip valid -> no predicates in hot path
    for (; i + 4 <= rem; i += 4) {
        float4 w0 = *(const float4*)(xl + (size_t)n0 * DD + sub * 4);
        float4 w1 = *(const float4*)(xl + (size_t)n1 * DD + sub * 4);
        int m0 = __ldg(ip + i + 8 + half);
        int m1 = __ldg(ip + i + 10 + half);

        float u, l0 = 0.f, b0f = 0.f, l1 = 0.f, b1f = 0.f;
        u = v0.x + xrv.x; l0 = fmaf(attv.x, u, l0); b0f = fmaf(attv.x, fabsf(u), b0f);
        u = v0.y + xrv.y; l0 = fmaf(attv.y, u, l0); b0f = fmaf(attv.y, fabsf(u), b0f);
        u = v0.z + xrv.z; l0 = fmaf(attv.z, u, l0); b0f = fmaf(attv.z, fabsf(u), b0f);
        u = v0.w + xrv.w; l0 = fmaf(attv.w, u, l0); b0f = fmaf(attv.w, fabsf(u), b0f);
        u = v1.x + xrv.x; l1 = fmaf(attv.x, u, l1); b1f = fmaf(attv.x, fabsf(u), b1f);
        u = v1.y + xrv.y; l1 = fmaf(attv.y, u, l1); b1f = fmaf(attv.y, fabsf(u), b1f);
        u = v1.z + xrv.z; l1 = fmaf(attv.z, u, l1); b1f = fmaf(attv.z, fabsf(u), b1f);
        u = v1.w + xrv.w; l1 = fmaf(attv.w, u, l1); b1f = fmaf(attv.w, fabsf(u), b1f);
        float t0 = fmaf(0.6f, l0, 0.4f * b0f);
        float t1 = fmaf(0.6f, l1, 0.4f * b1f);

        t0 += __shfl_xor_sync(0xffffffffu, t0, 1);
        t1 += __shfl_xor_sync(0xffffffffu, t1, 1);
        t0 += __shfl_xor_sync(0xffffffffu, t0, 2);
        t1 += __shfl_xor_sync(0xffffffffu, t1, 2);

        float p0 = __expf(t0);
        float p1 = __expf(t1);
        s += p0 + p1;
        a0 = fmaf(p0, v0.x, fmaf(p1, v1.x, a0));
        a1 = fmaf(p0, v0.y, fmaf(p1, v1.y, a1));
        a2 = fmaf(p0, v0.z, fmaf(p1, v1.z, a2));
        a3 = fmaf(p0, v0.w, fmaf(p1, v1.w, a3));

        v0 = w0; v1 = w1; n0 = m0; n1 = m1;
    }

    // predicated tail trip (0 < rem - i < 4), uses already-prefetched v0/v1
    if (i < rem) {
        float u, l0 = 0.f, b0f = 0.f, l1 = 0.f, b1f = 0.f;
        u = v0.x + xrv.x; l0 = fmaf(attv.x, u, l0); b0f = fmaf(attv.x, fabsf(u), b0f);
        u = v0.y + xrv.y; l0 = fmaf(attv.y, u, l0); b0f = fmaf(attv.y, fabsf(u), b0f);
        u = v0.z + xrv.z; l0 = fmaf(attv.z, u, l0); b0f = fmaf(attv.z, fabsf(u), b0f);
        u = v0.w + xrv.w; l0 = fmaf(attv.w, u, l0); b0f = fmaf(attv.w, fabsf(u), b0f);
        u = v1.x + xrv.x; l1 = fmaf(attv.x, u, l1); b1f = fmaf(attv.x, fabsf(u), b1f);
        u = v1.y + xrv.y; l1 = fmaf(attv.y, u, l1); b1f = fmaf(attv.y, fabsf(u), b1f);
        u = v1.z + xrv.z; l1 = fmaf(attv.z, u, l1); b1f = fmaf(attv.z, fabsf(u), b1f);
        u = v1.w + xrv.w; l1 = fmaf(attv.w, u, l1); b1f = fmaf(attv.w, fabsf(u), b1f);
        float t0 = fmaf(0.6f, l0, 0.4f * b0f);
        float t1 = fmaf(0.6f, l1, 0.4f * b1f);

        t0 += __shfl_xor_sync(0xffffffffu, t0, 1);
        t1 += __shfl_xor_sync(0xffffffffu, t1, 1);
        t0 += __shfl_xor_sync(0xffffffffu, t0, 2);
        t1 += __shfl_xor_sync(0xffffffffu, t1, 2);

        float p0 = (i + half     < rem) ? __expf(t0) : 0.f;
        float p1 = (i + 2 + half < rem) ? __expf(t1) : 0.f;
        s += p0 + p1;
        a0 = fmaf(p0, v0.x, fmaf(p1, v1.x, a0));
        a1 = fmaf(p0, v0.y, fmaf(p1, v1.y, a1));
        a2 = fmaf(p0, v0.z, fmaf(p1, v1.z, a2));
        a3 = fmaf(p0, v0.w, fmaf(p1, v1.w, a3));
    }

    // combine the two half-warps (disjoint edge sets, same dims)
    s  += __shfl_xor_sync(0xffffffffu, s,  16);
    a0 += __shfl_xor_sync(0xffffffffu, a0, 16);
    a1 += __shfl_xor_sync(0xffffffffu, a1, 16);
    a2 += __shfl_xor_sync(0xffffffffu, a2, 16);
    a3 += __shfl_xor_sync(0xffffffffu, a3, 16);

    if (half == 0) {
        float4 bv = *(const float4*)(bias + sub * 4);
        float inv = __fdividef(1.f, s);
        float4 o;
        o.x = fmaxf(fmaf(a0, inv, bv.x), 0.f);
        o.y = fmaxf(fmaf(a1, inv, bv.y), 0.f);
        o.z = fmaxf(fmaf(a2, inv, bv.z), 0.f);
        o.w = fmaxf(fmaf(a3, inv, bv.w), 0.f);
        *(float4*)(out + (size_t)w * DD + sub * 4) = o;
    }
}

// ---------------- launch ----------------
extern "C" void kernel_launch(void* const* d_in, const int* in_sizes, int n_in,
                              void* d_out, int out_size) {
    const float* x    = (const float*)d_in[0];
    const int*   edge = (const int*)  d_in[1];
    const float* W1l  = (const float*)d_in[2];
    const float* W1r  = (const float*)d_in[3];
    const float* att1 = (const float*)d_in[4];
    const float* b1   = (const float*)d_in[5];
    const float* W2l  = (const float*)d_in[6];
    const float* W2r  = (const float*)d_in[7];
    const float* att2 = (const float*)d_in[8];
    const float* b2   = (const float*)d_in[9];

    int E = in_sizes[1] / 2;
    int N = in_sizes[0] / FF;
    const int* srcp = edge;
    const int* dstp = edge + E;
    float* out = (float*)d_out;

    float *xl, *xr, *h1;
    cudaGetSymbolAddress((void**)&xl, g_xl);
    cudaGetSymbolAddress((void**)&xr, g_xr);
    cudaGetSymbolAddress((void**)&h1, g_h1);

    const int TB = 256;
    int gGemm = (N + 127) / 128;
    int gHalf1 = gGemm / 2;
    int gHalf2 = gGemm - gHalf1;
    int gEdge8 = (E + TB * 8 - 1) / (TB * 8);
    int nblk  = (N + NODES_PER_BLK - 1) / NODES_PER_BLK;
    int gNode = (N * 32 + TB - 1) / TB;
    int gFat1 = 2 * (gHalf1 > gEdge8 ? gHalf1 : gEdge8);
    int gFat2 = 2 * (gHalf2 > gEdge8 ? gHalf2 : gEdge8);

    // 1: gemm1 rows [0, N/2) + degree histogram (interleaved by block parity)
    fat_gemm_hist<<<gFat1, TB>>>(x, W1l, W1r, xl, xr, N, dstp, E, 0, gHalf1, gEdge8);
    // 2: CSR offsets via decoupled lookback (restores g_deg)
    scan_lookback<<<nblk, TB>>>(N, nblk);
    // 3: gemm1 rows [N/2, N) + CSR scatter (restores g_flag)
    fat_gemm_scatter<<<gFat2, TB>>>(x, W1l, W1r, xl, xr, N, srcp, dstp, E,
                                    gHalf1, gHalf2, gEdge8);
    // 4: layer-1 attention (profiled slot)
    gat_node<<<gNode, TB>>>(xl, xr, att1, b1, h1, N);
    // 5: layer-2 GEMM
    gemm_tiled<DD><<<gGemm, TB>>>(h1, W2l, W2r, xl, xr, N);
    // 6: layer-2 attention
    gat_node<<<gNode, TB>>>(xl, xr, att2, b2, out, N);
}